// round 3
// baseline (speedup 1.0000x reference)
#include <cuda_runtime.h>

#define NB 512
#define C_IN 32
#define F1 64
#define F2 128
#define BN_EPS 1e-5f
#define PARTS 8            // part-blocks per segment
#define TB 64              // tail grid (co-resident -> spin barrier safe)
#define TT 256

// ---- scratch (no allocations allowed) ----
__device__ float g_part[PARTS * NB * C_IN];   // per-part channel sums
__device__ float g_mean[NB * C_IN];           // per-segment means
__device__ float g_hT[F1 * NB];               // fc1 activations, TRANSPOSED [col][row]
__device__ float g_s1[F1], g_o1[F1];          // BN1 affine
__device__ unsigned g_barcnt;

// ---------------------------------------------------------------------------
// K1: segment partial sums. 4096 blocks = 512 segments x 8 parts.
// Each block computes its own segment offset (redundant 512-int reduction),
// then streams its 1/8 slice of the segment with 4 loads in flight.
// ---------------------------------------------------------------------------
__global__ void __launch_bounds__(256) k_segpart(const float4* __restrict__ x,
                                                 const int* __restrict__ len) {
    int bid = blockIdx.x;
    int seg = bid >> 3;          // parts of one segment are adjacent bids
    int p   = bid & (PARTS - 1);
    int tid = threadIdx.x;

    if (bid == 0 && tid == 0) g_barcnt = 0;   // reset tail barrier (stream-ordered)

    // --- segment offset: sum of len[i] for i < seg ---
    __shared__ int sl[256];
    int v = 0;
    if (tid < seg)       v += len[tid];
    if (tid + 256 < seg) v += len[tid + 256];
    sl[tid] = v;
    __syncthreads();
    #pragma unroll
    for (int st = 128; st > 0; st >>= 1) {
        if (tid < st) sl[tid] += sl[tid + st];
        __syncthreads();
    }
    int off = sl[0];
    int L   = len[seg];
    int r0  = off + (L * p)       / PARTS;
    int r1  = off + (L * (p + 1)) / PARTS;

    // --- stream rows [r0, r1): 4 independent float4 loads in flight ---
    int js = r0 * 8 + tid;
    int je = r1 * 8;
    float4 a0 = make_float4(0.f,0.f,0.f,0.f);
    float4 a1 = a0, a2 = a0, a3 = a0;
    int j = js;
    for (; j + 768 < je; j += 1024) {
        float4 v0 = __ldcs(&x[j]);
        float4 v1 = __ldcs(&x[j + 256]);
        float4 v2 = __ldcs(&x[j + 512]);
        float4 v3 = __ldcs(&x[j + 768]);
        a0.x += v0.x; a0.y += v0.y; a0.z += v0.z; a0.w += v0.w;
        a1.x += v1.x; a1.y += v1.y; a1.z += v1.z; a1.w += v1.w;
        a2.x += v2.x; a2.y += v2.y; a2.z += v2.z; a2.w += v2.w;
        a3.x += v3.x; a3.y += v3.y; a3.z += v3.z; a3.w += v3.w;
    }
    for (; j < je; j += 256) {
        float4 v0 = __ldcs(&x[j]);
        a0.x += v0.x; a0.y += v0.y; a0.z += v0.z; a0.w += v0.w;
    }
    a0.x += a1.x + a2.x + a3.x;  // fixed order, deterministic
    a0.y += a1.y + a2.y + a3.y;
    a0.z += a1.z + a2.z + a3.z;
    a0.w += a1.w + a2.w + a3.w;

    // --- tree reduce preserving channel-quad class (tid & 7) ---
    __shared__ float4 red[256];
    red[tid] = a0;
    __syncthreads();
    #pragma unroll
    for (int st = 128; st >= 8; st >>= 1) {
        if (tid < st) {
            float4 o = red[tid + st];
            red[tid].x += o.x; red[tid].y += o.y;
            red[tid].z += o.z; red[tid].w += o.w;
        }
        __syncthreads();
    }
    if (tid < 8) {
        ((float4*)g_part)[(p * NB + seg) * 8 + tid] = red[tid];
    }
}

// ---------------------------------------------------------------------------
// software grid barrier (TB blocks, all co-resident)
// ---------------------------------------------------------------------------
__device__ __forceinline__ void grid_bar(unsigned target) {
    __syncthreads();
    if (threadIdx.x == 0) {
        __threadfence();
        atomicAdd(&g_barcnt, 1u);
        while (*((volatile unsigned*)&g_barcnt) < target) { }
        __threadfence();
    }
    __syncthreads();
}

// ---------------------------------------------------------------------------
// K2: fused tail, 64 blocks x 256 threads, TWO grid barriers total.
//   A0: reduce parts -> g_mean          (block b owns rows 8b..8b+7)
//   A : fc1 column + BN1 stats          (block b owns column b; block-local)
//   B : BN1+relu+fc2+BN2 stats+apply    (block b owns out cols 2b,2b+1; local)
// ---------------------------------------------------------------------------
__global__ void __launch_bounds__(TT) k_tail(
    const int*   __restrict__ len,
    const float* __restrict__ W1, const float* __restrict__ b1,
    const float* __restrict__ g1, const float* __restrict__ be1,
    const float* __restrict__ W2, const float* __restrict__ b2,
    const float* __restrict__ g2, const float* __restrict__ be2,
    float* __restrict__ out)
{
    __shared__ float sW2[F1 * F2];     // 32 KiB
    __shared__ float sred[2 * TT];
    __shared__ float ss1[F1], so1[F1];
    __shared__ float sbn2[4];

    int tid = threadIdx.x;
    int b   = blockIdx.x;

    // ---- A0: g_mean rows 8b..8b+7 = (sum over parts) / len ----
    {
        int row = 8 * b + (tid >> 5);
        int ch  = tid & 31;
        float s = 0.f;
        #pragma unroll
        for (int p = 0; p < PARTS; p++)
            s += g_part[(p * NB + row) * C_IN + ch];
        g_mean[row * C_IN + ch] = s / (float)len[row];
    }
    // preload W2 into smem (independent of A0/A results)
    for (int i = tid; i < (F1 * F2) / 4; i += TT)
        ((float4*)sW2)[i] = ((const float4*)W2)[i];

    grid_bar(1 * TB);

    // ---- A: column c=b of h = mean @ W1 + b1, plus BN1 stats ----
    {
        int c = b;
        float acc0 = b1[c], acc1 = acc0;
        const float* m0 = &g_mean[tid * C_IN];
        const float* m1 = &g_mean[(tid + 256) * C_IN];
        #pragma unroll
        for (int k = 0; k < C_IN; k++) {
            float w = __ldg(&W1[k * F1 + c]);   // uniform across block
            acc0 = fmaf(m0[k], w, acc0);
            acc1 = fmaf(m1[k], w, acc1);
        }
        g_hT[c * NB + tid]       = acc0;
        g_hT[c * NB + tid + 256] = acc1;

        sred[tid]      = acc0 + acc1;
        sred[TT + tid] = acc0 * acc0 + acc1 * acc1;
        __syncthreads();
        #pragma unroll
        for (int st = 128; st > 0; st >>= 1) {
            if (tid < st) {
                sred[tid]      += sred[tid + st];
                sred[TT + tid] += sred[TT + tid + st];
            }
            __syncthreads();
        }
        if (tid == 0) {
            float mu  = sred[0]  * (1.0f / (float)NB);
            float var = sred[TT] * (1.0f / (float)NB) - mu * mu;
            float sc  = g1[c] * rsqrtf(var + BN_EPS);
            g_s1[c] = sc;
            g_o1[c] = be1[c] - mu * sc;
        }
    }
    grid_bar(2 * TB);

    if (tid < F1) { ss1[tid] = g_s1[tid]; so1[tid] = g_o1[tid]; }
    __syncthreads();

    // ---- B: out cols c0=2b, c1=2b+1; rows tid and tid+256 per thread ----
    {
        int c0 = 2 * b, c1 = 2 * b + 1;
        float a00 = b2[c0], a01 = b2[c1];   // row tid
        float a10 = a00,    a11 = a01;      // row tid+256
        a10 = b2[c0]; a11 = b2[c1];
        #pragma unroll 8
        for (int k = 0; k < F1; k++) {
            float h0 = g_hT[k * NB + tid];
            float h1 = g_hT[k * NB + tid + 256];
            float sc = ss1[k], of = so1[k];
            float r0 = fmaxf(fmaf(h0, sc, of), 0.f);
            float r1 = fmaxf(fmaf(h1, sc, of), 0.f);
            float w0 = sW2[k * F2 + c0];
            float w1 = sW2[k * F2 + c1];
            a00 = fmaf(r0, w0, a00);
            a01 = fmaf(r0, w1, a01);
            a10 = fmaf(r1, w0, a10);
            a11 = fmaf(r1, w1, a11);
        }

        // block-local BN2 stats for both columns (deterministic tree)
        sred[tid]      = a00 + a10;               // sum col c0
        sred[TT + tid] = a00 * a00 + a10 * a10;   // sumsq col c0
        __syncthreads();
        #pragma unroll
        for (int st = 128; st > 0; st >>= 1) {
            if (tid < st) {
                sred[tid]      += sred[tid + st];
                sred[TT + tid] += sred[TT + tid + st];
            }
            __syncthreads();
        }
        if (tid == 0) {
            float mu  = sred[0]  * (1.0f / (float)NB);
            float var = sred[TT] * (1.0f / (float)NB) - mu * mu;
            float sc  = g2[c0] * rsqrtf(var + BN_EPS);
            sbn2[0] = sc;
            sbn2[1] = be2[c0] - mu * sc;
        }
        __syncthreads();

        sred[tid]      = a01 + a11;               // sum col c1
        sred[TT + tid] = a01 * a01 + a11 * a11;   // sumsq col c1
        __syncthreads();
        #pragma unroll
        for (int st = 128; st > 0; st >>= 1) {
            if (tid < st) {
                sred[tid]      += sred[tid + st];
                sred[TT + tid] += sred[TT + tid + st];
            }
            __syncthreads();
        }
        if (tid == 0) {
            float mu  = sred[0]  * (1.0f / (float)NB);
            float var = sred[TT] * (1.0f / (float)NB) - mu * mu;
            float sc  = g2[c1] * rsqrtf(var + BN_EPS);
            sbn2[2] = sc;
            sbn2[3] = be2[c1] - mu * sc;
        }
        __syncthreads();

        float s0 = sbn2[0], o0 = sbn2[1], s1 = sbn2[2], o1 = sbn2[3];
        out[tid * F2 + c0]         = fmaf(a00, s0, o0);
        out[tid * F2 + c1]         = fmaf(a01, s1, o1);
        out[(tid + 256) * F2 + c0] = fmaf(a10, s0, o0);
        out[(tid + 256) * F2 + c1] = fmaf(a11, s1, o1);
    }
}

// ---------------------------------------------------------------------------
extern "C" void kernel_launch(void* const* d_in, const int* in_sizes, int n_in,
                              void* d_out, int out_size) {
    const float* x     = (const float*)d_in[0];
    const int*   len   = (const int*)  d_in[1];
    const float* W1    = (const float*)d_in[2];
    const float* b1    = (const float*)d_in[3];
    const float* g1    = (const float*)d_in[4];
    const float* beta1 = (const float*)d_in[5];
    const float* W2    = (const float*)d_in[6];
    const float* b2    = (const float*)d_in[7];
    const float* g2    = (const float*)d_in[8];
    const float* beta2 = (const float*)d_in[9];
    float* out = (float*)d_out;

    k_segpart<<<NB * PARTS, 256>>>((const float4*)x, len);
    k_tail<<<TB, TT>>>(len, W1, b1, g1, beta1, W2, b2, g2, beta2, out);
}

// round 4
// speedup vs baseline: 1.1314x; 1.1314x over previous
#include <cuda_runtime.h>

#define NB 512
#define C_IN 32
#define F1 64
#define F2 128
#define BN_EPS 1e-5f
#define PARTS 8            // part-blocks per segment
#define TB 64              // tail grid (co-resident -> spin barrier safe)
#define TT 256

// ---- scratch (no allocations allowed) ----
__device__ float g_part[PARTS * NB * C_IN];   // per-part channel sums
__device__ float g_meanT[C_IN * NB];          // per-segment means, TRANSPOSED [ch][row]
__device__ float g_hT[F1 * NB];               // fc1 activations, TRANSPOSED [col][row]
__device__ float g_s1[F1], g_o1[F1];          // BN1 affine
__device__ unsigned g_barcnt;

// ---------------------------------------------------------------------------
// K1: segment partial sums. 4096 blocks = 512 segments x 8 parts.
// Each block computes its own segment offset (redundant 512-int reduction),
// then streams its 1/8 slice of the segment with 4 loads in flight.
// ---------------------------------------------------------------------------
__global__ void __launch_bounds__(256) k_segpart(const float4* __restrict__ x,
                                                 const int* __restrict__ len) {
    int bid = blockIdx.x;
    int seg = bid >> 3;          // parts of one segment are adjacent bids
    int p   = bid & (PARTS - 1);
    int tid = threadIdx.x;

    if (bid == 0 && tid == 0) g_barcnt = 0;   // reset tail barrier (stream-ordered)

    // --- segment offset: sum of len[i] for i < seg ---
    __shared__ int sl[256];
    int v = 0;
    if (tid < seg)       v += len[tid];
    if (tid + 256 < seg) v += len[tid + 256];
    sl[tid] = v;
    __syncthreads();
    #pragma unroll
    for (int st = 128; st > 0; st >>= 1) {
        if (tid < st) sl[tid] += sl[tid + st];
        __syncthreads();
    }
    int off = sl[0];
    int L   = len[seg];
    int r0  = off + (L * p)       / PARTS;
    int r1  = off + (L * (p + 1)) / PARTS;

    // --- stream rows [r0, r1): 4 independent float4 loads in flight ---
    int js = r0 * 8 + tid;
    int je = r1 * 8;
    float4 a0 = make_float4(0.f,0.f,0.f,0.f);
    float4 a1 = a0, a2 = a0, a3 = a0;
    int j = js;
    for (; j + 768 < je; j += 1024) {
        float4 v0 = __ldcs(&x[j]);
        float4 v1 = __ldcs(&x[j + 256]);
        float4 v2 = __ldcs(&x[j + 512]);
        float4 v3 = __ldcs(&x[j + 768]);
        a0.x += v0.x; a0.y += v0.y; a0.z += v0.z; a0.w += v0.w;
        a1.x += v1.x; a1.y += v1.y; a1.z += v1.z; a1.w += v1.w;
        a2.x += v2.x; a2.y += v2.y; a2.z += v2.z; a2.w += v2.w;
        a3.x += v3.x; a3.y += v3.y; a3.z += v3.z; a3.w += v3.w;
    }
    for (; j < je; j += 256) {
        float4 v0 = __ldcs(&x[j]);
        a0.x += v0.x; a0.y += v0.y; a0.z += v0.z; a0.w += v0.w;
    }
    a0.x += a1.x + a2.x + a3.x;  // fixed order, deterministic
    a0.y += a1.y + a2.y + a3.y;
    a0.z += a1.z + a2.z + a3.z;
    a0.w += a1.w + a2.w + a3.w;

    // --- tree reduce preserving channel-quad class (tid & 7) ---
    __shared__ float4 red[256];
    red[tid] = a0;
    __syncthreads();
    #pragma unroll
    for (int st = 128; st >= 8; st >>= 1) {
        if (tid < st) {
            float4 o = red[tid + st];
            red[tid].x += o.x; red[tid].y += o.y;
            red[tid].z += o.z; red[tid].w += o.w;
        }
        __syncthreads();
    }
    if (tid < 8) {
        ((float4*)g_part)[(p * NB + seg) * 8 + tid] = red[tid];
    }
}

// ---------------------------------------------------------------------------
// software grid barrier (TB blocks, all co-resident)
// ---------------------------------------------------------------------------
__device__ __forceinline__ void grid_bar(unsigned target) {
    __syncthreads();
    if (threadIdx.x == 0) {
        __threadfence();
        atomicAdd(&g_barcnt, 1u);
        while (*((volatile unsigned*)&g_barcnt) < target) { }
        __threadfence();
    }
    __syncthreads();
}

// ---------------------------------------------------------------------------
// K2: fused tail, 64 blocks x 256 threads, TWO grid barriers.
//   A0: reduce parts -> g_meanT (transposed)   block b owns rows 8b..8b+7
//   A : fc1 column + BN1 stats                 block b owns column b
//   B : BN1+relu+fc2+BN2 stats+apply           block b owns out cols 2b,2b+1
// All global traffic is coalesced: g_meanT / g_hT are [feature][row] so
// consecutive threads (rows) hit consecutive addresses; weights are
// warp-uniform broadcasts.
// ---------------------------------------------------------------------------
__global__ void __launch_bounds__(TT) k_tail(
    const int*   __restrict__ len,
    const float* __restrict__ W1, const float* __restrict__ b1,
    const float* __restrict__ g1, const float* __restrict__ be1,
    const float* __restrict__ W2, const float* __restrict__ b2,
    const float* __restrict__ g2, const float* __restrict__ be2,
    float* __restrict__ out)
{
    __shared__ float sW2[F1 * F2];     // 32 KiB
    __shared__ float sred[2 * TT];
    __shared__ float ss1[F1], so1[F1];
    __shared__ float sbn2[4];

    int tid = threadIdx.x;
    int b   = blockIdx.x;

    // ---- A0: g_meanT for rows 8b..8b+7 ----
    {
        int ch  = tid >> 3;            // 0..31
        int row = 8 * b + (tid & 7);   // 8 consecutive rows
        float s = 0.f;
        #pragma unroll
        for (int p = 0; p < PARTS; p++)
            s += g_part[(p * NB + row) * C_IN + ch];
        g_meanT[ch * NB + row] = s / (float)len[row];
    }
    // preload W2 into smem (independent of A0/A results)
    for (int i = tid; i < (F1 * F2) / 4; i += TT)
        ((float4*)sW2)[i] = ((const float4*)W2)[i];

    grid_bar(1 * TB);

    // ---- A: column c=b of h = mean @ W1 + b1, plus BN1 stats ----
    {
        int c = b;
        float acc0 = b1[c], acc1 = acc0;
        #pragma unroll
        for (int k = 0; k < C_IN; k++) {
            float w = __ldg(&W1[k * F1 + c]);          // warp-uniform
            acc0 = fmaf(g_meanT[k * NB + tid],       w, acc0);   // coalesced
            acc1 = fmaf(g_meanT[k * NB + tid + 256], w, acc1);   // coalesced
        }
        g_hT[c * NB + tid]       = acc0;
        g_hT[c * NB + tid + 256] = acc1;

        sred[tid]      = acc0 + acc1;
        sred[TT + tid] = acc0 * acc0 + acc1 * acc1;
        __syncthreads();
        #pragma unroll
        for (int st = 128; st > 0; st >>= 1) {
            if (tid < st) {
                sred[tid]      += sred[tid + st];
                sred[TT + tid] += sred[TT + tid + st];
            }
            __syncthreads();
        }
        if (tid == 0) {
            float mu  = sred[0]  * (1.0f / (float)NB);
            float var = sred[TT] * (1.0f / (float)NB) - mu * mu;
            float sc  = g1[c] * rsqrtf(var + BN_EPS);
            g_s1[c] = sc;
            g_o1[c] = be1[c] - mu * sc;
        }
    }
    grid_bar(2 * TB);

    if (tid < F1) { ss1[tid] = g_s1[tid]; so1[tid] = g_o1[tid]; }
    __syncthreads();

    // ---- B: out cols c0=2b, c1=2b+1; rows tid and tid+256 per thread ----
    {
        int c0 = 2 * b, c1 = 2 * b + 1;
        float a00 = b2[c0], a01 = b2[c1];   // row tid
        float a10 = b2[c0], a11 = b2[c1];   // row tid+256
        #pragma unroll 8
        for (int k = 0; k < F1; k++) {
            float h0 = g_hT[k * NB + tid];         // coalesced
            float h1 = g_hT[k * NB + tid + 256];   // coalesced
            float sc = ss1[k], of = so1[k];
            float r0 = fmaxf(fmaf(h0, sc, of), 0.f);
            float r1 = fmaxf(fmaf(h1, sc, of), 0.f);
            float w0 = sW2[k * F2 + c0];
            float w1 = sW2[k * F2 + c1];
            a00 = fmaf(r0, w0, a00);
            a01 = fmaf(r0, w1, a01);
            a10 = fmaf(r1, w0, a10);
            a11 = fmaf(r1, w1, a11);
        }

        // block-local BN2 stats for col c0 (deterministic tree)
        sred[tid]      = a00 + a10;
        sred[TT + tid] = a00 * a00 + a10 * a10;
        __syncthreads();
        #pragma unroll
        for (int st = 128; st > 0; st >>= 1) {
            if (tid < st) {
                sred[tid]      += sred[tid + st];
                sred[TT + tid] += sred[TT + tid + st];
            }
            __syncthreads();
        }
        if (tid == 0) {
            float mu  = sred[0]  * (1.0f / (float)NB);
            float var = sred[TT] * (1.0f / (float)NB) - mu * mu;
            float sc  = g2[c0] * rsqrtf(var + BN_EPS);
            sbn2[0] = sc;
            sbn2[1] = be2[c0] - mu * sc;
        }
        __syncthreads();

        // col c1
        sred[tid]      = a01 + a11;
        sred[TT + tid] = a01 * a01 + a11 * a11;
        __syncthreads();
        #pragma unroll
        for (int st = 128; st > 0; st >>= 1) {
            if (tid < st) {
                sred[tid]      += sred[tid + st];
                sred[TT + tid] += sred[TT + tid + st];
            }
            __syncthreads();
        }
        if (tid == 0) {
            float mu  = sred[0]  * (1.0f / (float)NB);
            float var = sred[TT] * (1.0f / (float)NB) - mu * mu;
            float sc  = g2[c1] * rsqrtf(var + BN_EPS);
            sbn2[2] = sc;
            sbn2[3] = be2[c1] - mu * sc;
        }
        __syncthreads();

        float s0 = sbn2[0], o0 = sbn2[1], s1 = sbn2[2], o1 = sbn2[3];
        out[tid * F2 + c0]         = fmaf(a00, s0, o0);
        out[tid * F2 + c1]         = fmaf(a01, s1, o1);
        out[(tid + 256) * F2 + c0] = fmaf(a10, s0, o0);
        out[(tid + 256) * F2 + c1] = fmaf(a11, s1, o1);
    }
}

// ---------------------------------------------------------------------------
extern "C" void kernel_launch(void* const* d_in, const int* in_sizes, int n_in,
                              void* d_out, int out_size) {
    const float* x     = (const float*)d_in[0];
    const int*   len   = (const int*)  d_in[1];
    const float* W1    = (const float*)d_in[2];
    const float* b1    = (const float*)d_in[3];
    const float* g1    = (const float*)d_in[4];
    const float* beta1 = (const float*)d_in[5];
    const float* W2    = (const float*)d_in[6];
    const float* b2    = (const float*)d_in[7];
    const float* g2    = (const float*)d_in[8];
    const float* beta2 = (const float*)d_in[9];
    float* out = (float*)d_out;

    k_segpart<<<NB * PARTS, 256>>>((const float4*)x, len);
    k_tail<<<TB, TT>>>(len, W1, b1, g1, beta1, W2, b2, g2, beta2, out);
}